// round 16
// baseline (speedup 1.0000x reference)
#include <cuda_runtime.h>
#include <cuda_bf16.h>
#include <math.h>
#include <stdint.h>

// Problem constants
#define BB   2
#define SS   2048
#define EE   1024
#define HH   16
#define DD   64
#define HALF 32
#define MROWS 4096            // B*S
#define NQKV  1152            // H*D + D + D
#define EPSF  1.1920929e-07f  // finfo(float32).eps

// ---------------- device scratch (static, allocation-free) ----------------
__device__ float g_Wqkv[1024 * NQKV];   // packed [Wq|Wk|Wv], tf32 bits
__device__ float g_Wo[EE * EE];         // Wo, tf32 bits
__device__ float g_xtf[MROWS * EE];     // x, tf32 bits
__device__ float g_gate[MROWS];         // 2*sigmoid(x[:32]@Wg)
__device__ float g_qkv[MROWS * NQKV];   // projections (fp32), rope/normed
__device__ float g_attn[MROWS * EE];    // attention output, tf32 bits

// ---------------- tf32 helpers ----------------
__device__ __forceinline__ uint32_t f2tf(float f) {
    uint32_t u;
    asm("cvt.rna.tf32.f32 %0, %1;" : "=r"(u) : "f"(f));
    return u;
}

__device__ __forceinline__ void mma_tf32(float c[4], const uint32_t a[4],
                                         const uint32_t b[2]) {
    asm volatile(
        "mma.sync.aligned.m16n8k8.row.col.f32.tf32.tf32.f32 "
        "{%0,%1,%2,%3}, {%4,%5,%6,%7}, {%8,%9}, {%0,%1,%2,%3};"
        : "+f"(c[0]), "+f"(c[1]), "+f"(c[2]), "+f"(c[3])
        : "r"(a[0]), "r"(a[1]), "r"(a[2]), "r"(a[3]), "r"(b[0]), "r"(b[1]));
}

// ---------------- pack Wq|Wk|Wv (tf32 bits) ----------------
__global__ void pack_kernel(const float* __restrict__ Wq,
                            const float* __restrict__ Wk,
                            const float* __restrict__ Wv,
                            float* __restrict__ Wqkv)
{
    int idx = blockIdx.x * blockDim.x + threadIdx.x;
    if (idx >= 1024 * NQKV) return;
    int k = idx / NQKV;
    int n = idx - k * NQKV;
    float v;
    if (n < 1024)       v = Wq[k * 1024 + n];
    else if (n < 1088)  v = Wk[k * 64 + (n - 1024)];
    else                v = Wv[k * 64 + (n - 1088)];
    Wqkv[idx] = __uint_as_float(f2tf(v));
}

// ---------------- generic fp32 -> tf32-bits conversion ----------------
__global__ void conv_tf_kernel(const float* __restrict__ src,
                               float* __restrict__ dst, int n)
{
    int i = blockIdx.x * blockDim.x + threadIdx.x;
    if (i < n) dst[i] = __uint_as_float(f2tf(src[i]));
}

// ---------------- gate: 2*sigmoid(x[:32]@Wg), one warp per row ----------
// EXACT replica of the old post_kernel reduction (bit-identical gates).
__global__ __launch_bounds__(256)
void gate_kernel(const float* __restrict__ x, const float* __restrict__ Wg,
                 float* __restrict__ gate)
{
    int wid  = (blockIdx.x * blockDim.x + threadIdx.x) >> 5;
    int lane = threadIdx.x & 31;
    if (wid >= MROWS) return;
    float g = x[(size_t)wid * EE + lane] * Wg[lane];
    #pragma unroll
    for (int off = 16; off; off >>= 1)
        g += __shfl_xor_sync(0xffffffffu, g, off);
    float gv = 2.0f / (1.0f + __expf(-g));
    if (lane == 0) gate[wid] = gv;
}

// ---------------- TF32 tensor-core GEMM, 2-stage, optional fused epilogue
// mode 0: plain store. mode 1 (QKV projection): fused RoPE+RMSNorm on q/k
// heads and gate*ve add on the v head — the warp tile (32 rows x 64 cols)
// aligns exactly with one head, so rope is thread-local and the norm is a
// 4-lane shfl. Eliminates the separate post_kernel pass over qkv.
#define GLD 136
#define ALD 24

__global__ __launch_bounds__(256, 2)
void gemm_tf32(const float* __restrict__ A, const float* __restrict__ B,
               float* __restrict__ C, int K, int lda, int ldb, int ldc,
               int mode,
               const float* __restrict__ ve, const float* __restrict__ cosb,
               const float* __restrict__ sinb, const float* __restrict__ gate)
{
    __shared__ uint32_t As[2][128 * ALD];   // [m][k-permuted]
    __shared__ uint32_t Bs[2][16 * GLD];    // [k][n]

    int tid  = threadIdx.x;
    int lane = tid & 31;
    int wid  = tid >> 5;
    int wm   = wid & 3;          // warp m index 0..3 (32 rows each)
    int wn   = wid >> 2;         // warp n index 0..1 (64 cols each)
    size_t m0 = (size_t)blockIdx.y * 128;
    size_t n0 = (size_t)blockIdx.x * 128;

    int arow = tid >> 1;         // 0..127
    int ak   = (tid & 1) * 8;    // 0 or 8
    int brow = tid >> 4;         // 0..15
    int bcol = (tid & 15) * 8;   // 0..120

    const float* Ap = A + (m0 + arow) * (size_t)lda + ak;
    const float* Bp = B + (size_t)brow * ldb + n0 + bcol;

    float4 a0n = *(const float4*)Ap;
    float4 a1n = *(const float4*)(Ap + 4);
    float4 b0n = *(const float4*)Bp;
    float4 b1n = *(const float4*)(Bp + 4);

    // prologue: fill stage 0
    *(uint4*)&As[0][arow * ALD + ak] =
        make_uint4(__float_as_uint(a0n.x), __float_as_uint(a1n.x),
                   __float_as_uint(a0n.y), __float_as_uint(a1n.y));
    *(uint4*)&As[0][arow * ALD + ak + 4] =
        make_uint4(__float_as_uint(a0n.z), __float_as_uint(a1n.z),
                   __float_as_uint(a0n.w), __float_as_uint(a1n.w));
    *(uint4*)&Bs[0][brow * GLD + bcol] =
        make_uint4(__float_as_uint(b0n.x), __float_as_uint(b0n.y),
                   __float_as_uint(b0n.z), __float_as_uint(b0n.w));
    *(uint4*)&Bs[0][brow * GLD + bcol + 4] =
        make_uint4(__float_as_uint(b1n.x), __float_as_uint(b1n.y),
                   __float_as_uint(b1n.z), __float_as_uint(b1n.w));
    __syncthreads();

    float acc[2][8][4];
    #pragma unroll
    for (int mt = 0; mt < 2; mt++)
        #pragma unroll
        for (int nt = 0; nt < 8; nt++)
            #pragma unroll
            for (int r = 0; r < 4; r++) acc[mt][nt][r] = 0.f;

    int ar = lane >> 2;          // 0..7
    int ac = lane & 3;           // 0..3
    int buf = 0;

    for (int k0 = 0; k0 < K; k0 += 16) {
        bool more = (k0 + 16 < K);
        if (more) {
            a0n = *(const float4*)(Ap + k0 + 16);
            a1n = *(const float4*)(Ap + k0 + 20);
            b0n = *(const float4*)(Bp + (size_t)(k0 + 16) * ldb);
            b1n = *(const float4*)(Bp + (size_t)(k0 + 16) * ldb + 4);
        }

        const uint32_t* Ab = As[buf];
        const uint32_t* Bb = Bs[buf];
        #pragma unroll
        for (int kk = 0; kk < 16; kk += 8) {
            uint32_t afr[2][4];
            #pragma unroll
            for (int mt = 0; mt < 2; mt++) {
                int mb = wm * 32 + mt * 16;
                uint2 u = *(const uint2*)&Ab[(mb + ar) * ALD + kk + 2 * ac];
                uint2 v = *(const uint2*)&Ab[(mb + 8 + ar) * ALD + kk + 2 * ac];
                afr[mt][0] = u.x; afr[mt][1] = v.x;
                afr[mt][2] = u.y; afr[mt][3] = v.y;
            }
            uint32_t bfr[8][2];
            #pragma unroll
            for (int nt = 0; nt < 8; nt++) {
                int nb = wn * 64 + nt * 8;
                bfr[nt][0] = Bb[(kk + ac) * GLD + nb + ar];
                bfr[nt][1] = Bb[(kk + 4 + ac) * GLD + nb + ar];
            }
            #pragma unroll
            for (int mt = 0; mt < 2; mt++)
                #pragma unroll
                for (int nt = 0; nt < 8; nt++)
                    mma_tf32(acc[mt][nt], afr[mt], bfr[nt]);
        }

        if (more) {
            int nb_ = buf ^ 1;
            *(uint4*)&As[nb_][arow * ALD + ak] =
                make_uint4(__float_as_uint(a0n.x), __float_as_uint(a1n.x),
                           __float_as_uint(a0n.y), __float_as_uint(a1n.y));
            *(uint4*)&As[nb_][arow * ALD + ak + 4] =
                make_uint4(__float_as_uint(a0n.z), __float_as_uint(a1n.z),
                           __float_as_uint(a0n.w), __float_as_uint(a1n.w));
            *(uint4*)&Bs[nb_][brow * GLD + bcol] =
                make_uint4(__float_as_uint(b0n.x), __float_as_uint(b0n.y),
                           __float_as_uint(b0n.z), __float_as_uint(b0n.w));
            *(uint4*)&Bs[nb_][brow * GLD + bcol + 4] =
                make_uint4(__float_as_uint(b1n.x), __float_as_uint(b1n.y),
                           __float_as_uint(b1n.z), __float_as_uint(b1n.w));
            __syncthreads();
            buf = nb_;
        }
    }

    if (mode == 0) {
        // plain epilogue
        #pragma unroll
        for (int mt = 0; mt < 2; mt++) {
            size_t row = m0 + wm * 32 + mt * 16 + ar;
            #pragma unroll
            for (int nt = 0; nt < 8; nt++) {
                size_t col = n0 + wn * 64 + nt * 8 + ac * 2;
                *(float2*)&C[row * (size_t)ldc + col] =
                    make_float2(acc[mt][nt][0], acc[mt][nt][1]);
                *(float2*)&C[(row + 8) * (size_t)ldc + col] =
                    make_float2(acc[mt][nt][2], acc[mt][nt][3]);
            }
        }
    } else {
        // fused QKV epilogue: this warp's 64-col half is exactly one head
        int colbase = (int)n0 + wn * 64;
        bool isv = (colbase == 1088);
        #pragma unroll
        for (int mt = 0; mt < 2; mt++) {
            #pragma unroll
            for (int rs = 0; rs < 2; rs++) {
                size_t row = m0 + wm * 32 + mt * 16 + ar + rs * 8;
                if (!isv) {
                    // rope + rmsnorm (q heads and the k head)
                    int s = (int)(row & (SS - 1));
                    float y[16];
                    float ssum = 0.f;
                    #pragma unroll
                    for (int nt = 0; nt < 4; nt++) {
                        #pragma unroll
                        for (int j = 0; j < 2; j++) {
                            int c = nt * 8 + ac * 2 + j;
                            float x1 = acc[mt][nt][rs * 2 + j];
                            float x2 = acc[mt][nt + 4][rs * 2 + j];
                            float cs = cosb[s * HALF + c];
                            float sn = sinb[s * HALF + c];
                            float y1 = x1 * cs + x2 * sn;
                            float y2 = x2 * cs - x1 * sn;
                            y[nt * 2 + j]     = y1;
                            y[8 + nt * 2 + j] = y2;
                            ssum += y1 * y1 + y2 * y2;
                        }
                    }
                    ssum += __shfl_xor_sync(0xffffffffu, ssum, 1);
                    ssum += __shfl_xor_sync(0xffffffffu, ssum, 2);
                    float sc = rsqrtf(ssum * (1.0f / 64.0f) + EPSF);
                    float* dst = &C[row * (size_t)ldc + colbase];
                    #pragma unroll
                    for (int nt = 0; nt < 4; nt++) {
                        #pragma unroll
                        for (int j = 0; j < 2; j++) {
                            int c = nt * 8 + ac * 2 + j;
                            dst[c]      = y[nt * 2 + j] * sc;
                            dst[c + 32] = y[8 + nt * 2 + j] * sc;
                        }
                    }
                } else {
                    // v head: add gate * ve
                    float gv = gate[row];
                    float* dst = &C[row * (size_t)ldc + colbase];
                    const float* veb = ve + row * (size_t)DD;
                    #pragma unroll
                    for (int nt = 0; nt < 8; nt++) {
                        #pragma unroll
                        for (int j = 0; j < 2; j++) {
                            int c = nt * 8 + ac * 2 + j;
                            dst[c] = acc[mt][nt][rs * 2 + j] + gv * veb[c];
                        }
                    }
                }
            }
        }
    }
}

// ---------------- windowed-causal flash attention, tf32 tensor cores v4 --
// (round-12 validated optimum, unchanged; g_attn writes tf32 bits)
#define TS 72
#define ATT_SMEM ((4 * 64 * TS) * 4)

__global__ __launch_bounds__(128)
void attn_kernel(const float* __restrict__ qkv, float* __restrict__ out,
                 const int* __restrict__ wptr)
{
    extern __shared__ uint32_t smu[];
    uint32_t* Qs = smu;                  // [64 q][TS]   k-permuted d cols
    uint32_t* Ks = Qs + 64 * TS;         // [64 key][TS] k-permuted d cols
    uint32_t* Vs = Ks + 64 * TS;         // [64 key][TS] natural
    uint32_t* Ps = Vs + 64 * TS;         // [64 q][TS]   k-permuted key cols

    const int window = *wptr;
    int tid  = threadIdx.x;
    int lane = tid & 31;
    int wid  = tid >> 5;          // 0..3
    int mb   = wid * 16;          // warp's q-block base (16 rows)
    int ar   = lane >> 2;         // 0..7
    int ac   = lane & 3;          // 0..3
    int r0   = mb + ar;           // this thread's q rows within the tile
    int r1   = r0 + 8;

    int qt = (SS / 64 - 1) - blockIdx.x;   // heavy tiles first
    int h  = blockIdx.y;
    int b  = blockIdx.z;
    int q0 = qt * 64;
    const float* base = qkv + (size_t)b * SS * NQKV;

    // Ps store positions for this thread's (col 2ac, col 2ac+1) pair
    int pp0 = (ac < 2) ? 4 * ac : 4 * ac - 7;

    // load Q tile [q][d] k-permuted (scaled, tf32)
    #pragma unroll
    for (int it = 0; it < 8; it++) {
        int idx = tid + it * 128;          // 0..1023 uint4 stores
        int row = idx >> 4;
        int sub = idx & 15;
        int g = sub >> 1, hh = sub & 1;
        const float* src = &base[(size_t)(q0 + row) * NQKV + h * 64 + g * 8 + 2 * hh];
        float2 a = *(const float2*)src;
        float2 c = *(const float2*)(src + 4);
        *(uint4*)&Qs[row * TS + g * 8 + 4 * hh] =
            make_uint4(f2tf(a.x * 0.125f), f2tf(c.x * 0.125f),
                       f2tf(a.y * 0.125f), f2tf(c.y * 0.125f));
    }

    float of[8][4];
    #pragma unroll
    for (int nb = 0; nb < 8; nb++)
        #pragma unroll
        for (int c = 0; c < 4; c++) of[nb][c] = 0.f;
    float m0r = -INFINITY, m1r = -INFINITY, l0r = 0.f, l1r = 0.f;

    int lo = q0 - window + 1; if (lo < 0) lo = 0;
    int t_lo = lo >> 6;

    for (int t = t_lo; t <= qt; t++) {
        int k0 = t * 64;
        __syncthreads();   // protect Ks/Vs from previous-iteration readers
        // K tile: k-permuted (same scheme as Q)
        #pragma unroll
        for (int it = 0; it < 8; it++) {
            int idx = tid + it * 128;
            int row = idx >> 4;
            int sub = idx & 15;
            int g = sub >> 1, hh = sub & 1;
            const float* src = &base[(size_t)(k0 + row) * NQKV + 1024 + g * 8 + 2 * hh];
            float2 a = *(const float2*)src;
            float2 c = *(const float2*)(src + 4);
            *(uint4*)&Ks[row * TS + g * 8 + 4 * hh] =
                make_uint4(f2tf(a.x), f2tf(c.x), f2tf(a.y), f2tf(c.y));
        }
        // V tile: natural layout, float4 path
        #pragma unroll
        for (int it = 0; it < 8; it++) {
            int idx = tid + it * 128;
            int row = idx >> 4;
            int d4 = (idx & 15) << 2;
            float4 v = *(const float4*)&base[(size_t)(k0 + row) * NQKV + 1088 + d4];
            *(uint4*)&Vs[row * TS + d4] =
                make_uint4(f2tf(v.x), f2tf(v.y), f2tf(v.z), f2tf(v.w));
        }
        __syncthreads();

        // ---- S = Q K^T on tensor cores (warp-local 16q x 64k) ----
        float sf[8][4];
        #pragma unroll
        for (int nb = 0; nb < 8; nb++)
            #pragma unroll
            for (int c = 0; c < 4; c++) sf[nb][c] = 0.f;
        #pragma unroll
        for (int kk = 0; kk < 64; kk += 8) {
            uint2 qa = *(const uint2*)&Qs[r0 * TS + kk + 2 * ac];
            uint2 qb = *(const uint2*)&Qs[r1 * TS + kk + 2 * ac];
            uint32_t afr[4] = {qa.x, qb.x, qa.y, qb.y};
            #pragma unroll
            for (int nb = 0; nb < 8; nb++) {
                int key = nb * 8 + ar;
                uint2 kv = *(const uint2*)&Ks[key * TS + kk + 2 * ac];
                uint32_t bfr[2] = {kv.x, kv.y};
                mma_tf32(sf[nb], afr, bfr);
            }
        }

        // ---- mask (boundary tiles only) ----
        bool need_mask = (k0 + 63 > q0) || (q0 + 63 - k0 >= window);
        if (need_mask) {
            int qg0 = q0 + r0, qg1 = q0 + r1;
            #pragma unroll
            for (int nb = 0; nb < 8; nb++) {
                int kg = k0 + nb * 8 + ac * 2;
                #pragma unroll
                for (int cc = 0; cc < 2; cc++) {
                    int kk = kg + cc;
                    int d0 = qg0 - kk, d1 = qg1 - kk;
                    if (d0 < 0 || d0 >= window) sf[nb][cc]     = -INFINITY;
                    if (d1 < 0 || d1 >= window) sf[nb][2 + cc] = -INFINITY;
                }
            }
        }

        // ---- online softmax (fp32, warp-local, branch-free dead rows) ----
        float pm0 = -INFINITY, pm1 = -INFINITY;
        #pragma unroll
        for (int nb = 0; nb < 8; nb++) {
            pm0 = fmaxf(pm0, fmaxf(sf[nb][0], sf[nb][1]));
            pm1 = fmaxf(pm1, fmaxf(sf[nb][2], sf[nb][3]));
        }
        pm0 = fmaxf(pm0, __shfl_xor_sync(0xffffffffu, pm0, 1));
        pm0 = fmaxf(pm0, __shfl_xor_sync(0xffffffffu, pm0, 2));
        pm1 = fmaxf(pm1, __shfl_xor_sync(0xffffffffu, pm1, 1));
        pm1 = fmaxf(pm1, __shfl_xor_sync(0xffffffffu, pm1, 2));
        float mnew0 = fmaxf(m0r, pm0);
        float mnew1 = fmaxf(m1r, pm1);
        float ms0 = (mnew0 == -INFINITY) ? 0.f : mnew0;
        float ms1 = (mnew1 == -INFINITY) ? 0.f : mnew1;

        float hs0 = 0.f, hs1 = 0.f;
        #pragma unroll
        for (int nb = 0; nb < 8; nb++) {
            int gbase = nb * 8;             // key group base
            float p0 = __expf(sf[nb][0] - ms0);
            float p1 = __expf(sf[nb][1] - ms0);
            float p2 = __expf(sf[nb][2] - ms1);
            float p3 = __expf(sf[nb][3] - ms1);
            hs0 += p0 + p1;
            hs1 += p2 + p3;
            Ps[r0 * TS + gbase + pp0]     = f2tf(p0);
            Ps[r0 * TS + gbase + pp0 + 2] = f2tf(p1);
            Ps[r1 * TS + gbase + pp0]     = f2tf(p2);
            Ps[r1 * TS + gbase + pp0 + 2] = f2tf(p3);
        }
        hs0 += __shfl_xor_sync(0xffffffffu, hs0, 1);
        hs0 += __shfl_xor_sync(0xffffffffu, hs0, 2);
        hs1 += __shfl_xor_sync(0xffffffffu, hs1, 1);
        hs1 += __shfl_xor_sync(0xffffffffu, hs1, 2);
        float corr0 = (m0r == -INFINITY) ? 0.f : __expf(m0r - ms0);
        float corr1 = (m1r == -INFINITY) ? 0.f : __expf(m1r - ms1);
        #pragma unroll
        for (int nb = 0; nb < 8; nb++) {
            of[nb][0] *= corr0; of[nb][1] *= corr0;
            of[nb][2] *= corr1; of[nb][3] *= corr1;
        }
        m0r = mnew0; m1r = mnew1;
        l0r = l0r * corr0 + hs0;
        l1r = l1r * corr1 + hs1;
        __syncwarp();   // Ps rows are warp-private

        // ---- O += P @ V on tensor cores (warp-local 16q x 64d) ----
        #pragma unroll
        for (int kk = 0; kk < 64; kk += 8) {
            uint2 pa = *(const uint2*)&Ps[r0 * TS + kk + 2 * ac];
            uint2 pb = *(const uint2*)&Ps[r1 * TS + kk + 2 * ac];
            uint32_t afr[4] = {pa.x, pb.x, pa.y, pb.y};
            #pragma unroll
            for (int nb = 0; nb < 8; nb++) {
                uint32_t bfr[2];
                bfr[0] = Vs[(kk + ac) * TS + nb * 8 + ar];
                bfr[1] = Vs[(kk + 4 + ac) * TS + nb * 8 + ar];
                mma_tf32(of[nb], afr, bfr);
            }
        }
    }

    // ---- finalize + write tf32 BITS (g_attn feeds gemm2's A operand) ----
    float inv0 = 1.0f / l0r;
    float inv1 = 1.0f / l1r;
    size_t row0 = (size_t)b * SS + q0 + r0;
    size_t row1 = (size_t)b * SS + q0 + r1;
    #pragma unroll
    for (int nb = 0; nb < 8; nb++) {
        size_t col = h * 64 + nb * 8 + ac * 2;
        *(float2*)&out[row0 * EE + col] =
            make_float2(__uint_as_float(f2tf(of[nb][0] * inv0)),
                        __uint_as_float(f2tf(of[nb][1] * inv0)));
        *(float2*)&out[row1 * EE + col] =
            make_float2(__uint_as_float(f2tf(of[nb][2] * inv1)),
                        __uint_as_float(f2tf(of[nb][3] * inv1)));
    }
}

// ---------------- launch ----------------
extern "C" void kernel_launch(void* const* d_in, const int* in_sizes, int n_in,
                              void* d_out, int out_size)
{
    const float* x    = (const float*)d_in[0];
    const float* ve   = (const float*)d_in[1];
    const float* cosb = (const float*)d_in[2];
    const float* sinb = (const float*)d_in[3];
    const float* Wq   = (const float*)d_in[4];
    const float* Wk   = (const float*)d_in[5];
    const float* Wv   = (const float*)d_in[6];
    const float* Wo   = (const float*)d_in[7];
    const float* Wg   = (const float*)d_in[8];
    const int*   win  = (const int*)d_in[9];
    float* out = (float*)d_out;

    float *wqkv, *wo_tf, *xtf, *gate, *qkv, *attn;
    cudaGetSymbolAddress((void**)&wqkv,  g_Wqkv);
    cudaGetSymbolAddress((void**)&wo_tf, g_Wo);
    cudaGetSymbolAddress((void**)&xtf,   g_xtf);
    cudaGetSymbolAddress((void**)&gate,  g_gate);
    cudaGetSymbolAddress((void**)&qkv,   g_qkv);
    cudaGetSymbolAddress((void**)&attn,  g_attn);

    cudaFuncSetAttribute(attn_kernel,
                         cudaFuncAttributeMaxDynamicSharedMemorySize,
                         (int)ATT_SMEM);

    // 1. pre-convert GEMM inputs + gate vector
    pack_kernel<<<(1024 * NQKV + 255) / 256, 256>>>(Wq, Wk, Wv, wqkv);
    conv_tf_kernel<<<(MROWS * EE + 255) / 256, 256>>>(x, xtf, MROWS * EE);
    conv_tf_kernel<<<(EE * EE + 255) / 256, 256>>>(Wo, wo_tf, EE * EE);
    gate_kernel<<<(MROWS * 32 + 255) / 256, 256>>>(x, Wg, gate);

    // 2. fused QKV projection + rope/rmsnorm/gate-ve epilogue
    gemm_tf32<<<dim3(NQKV / 128, MROWS / 128), 256>>>(
        xtf, wqkv, qkv, 1024, 1024, NQKV, NQKV, 1, ve, cosb, sinb, gate);

    // 3. attention (tf32 tensor core, warp-autonomous v4)
    attn_kernel<<<dim3(SS / 64, HH, BB), 128, ATT_SMEM>>>(qkv, attn, win);

    // 4. output projection (plain epilogue)
    gemm_tf32<<<dim3(EE / 128, MROWS / 128), 256>>>(
        attn, wo_tf, out, 1024, 1024, EE, EE, 0,
        nullptr, nullptr, nullptr, nullptr);
}

// round 17
// speedup vs baseline: 1.0240x; 1.0240x over previous
#include <cuda_runtime.h>
#include <cuda_bf16.h>
#include <math.h>
#include <stdint.h>

// Problem constants
#define BB   2
#define SS   2048
#define EE   1024
#define HH   16
#define DD   64
#define HALF 32
#define MROWS 4096            // B*S
#define NQKV  1152            // H*D + D + D
#define EPSF  1.1920929e-07f  // finfo(float32).eps

// ---------------- device scratch (static, allocation-free) ----------------
__device__ float g_Wqkv[1024 * NQKV];   // packed [Wq|Wk|Wv], tf32 bits
__device__ float g_Wo[EE * EE];         // Wo, tf32 bits
__device__ float g_xtf[MROWS * EE];     // x, tf32 bits
__device__ float g_qkv[MROWS * NQKV];   // projections (fp32), rope/normed
__device__ float g_attn[MROWS * EE];    // attention output, tf32 bits

// ---------------- tf32 helpers ----------------
__device__ __forceinline__ uint32_t f2tf(float f) {
    uint32_t u;
    asm("cvt.rna.tf32.f32 %0, %1;" : "=r"(u) : "f"(f));
    return u;
}

__device__ __forceinline__ void mma_tf32(float c[4], const uint32_t a[4],
                                         const uint32_t b[2]) {
    asm volatile(
        "mma.sync.aligned.m16n8k8.row.col.f32.tf32.tf32.f32 "
        "{%0,%1,%2,%3}, {%4,%5,%6,%7}, {%8,%9}, {%0,%1,%2,%3};"
        : "+f"(c[0]), "+f"(c[1]), "+f"(c[2]), "+f"(c[3])
        : "r"(a[0]), "r"(a[1]), "r"(a[2]), "r"(a[3]), "r"(b[0]), "r"(b[1]));
}

// ---------------- pack Wq|Wk|Wv (tf32 bits) ----------------
__global__ void pack_kernel(const float* __restrict__ Wq,
                            const float* __restrict__ Wk,
                            const float* __restrict__ Wv,
                            float* __restrict__ Wqkv)
{
    int idx = blockIdx.x * blockDim.x + threadIdx.x;
    if (idx >= 1024 * NQKV) return;
    int k = idx / NQKV;
    int n = idx - k * NQKV;
    float v;
    if (n < 1024)       v = Wq[k * 1024 + n];
    else if (n < 1088)  v = Wk[k * 64 + (n - 1024)];
    else                v = Wv[k * 64 + (n - 1088)];
    Wqkv[idx] = __uint_as_float(f2tf(v));
}

// ---------------- generic fp32 -> tf32-bits conversion ----------------
__global__ void conv_tf_kernel(const float* __restrict__ src,
                               float* __restrict__ dst, int n)
{
    int i = blockIdx.x * blockDim.x + threadIdx.x;
    if (i < n) dst[i] = __uint_as_float(f2tf(src[i]));
}

// ---------------- TF32 tensor-core GEMM v3: double-buffered (round 15) ----
#define GLD 136
#define ALD 24

__global__ __launch_bounds__(256, 2)
void gemm_tf32(const float* __restrict__ A, const float* __restrict__ B,
               float* __restrict__ C, int K, int lda, int ldb, int ldc)
{
    __shared__ uint32_t As[2][128 * ALD];   // [m][k-permuted]
    __shared__ uint32_t Bs[2][16 * GLD];    // [k][n]

    int tid  = threadIdx.x;
    int lane = tid & 31;
    int wid  = tid >> 5;
    int wm   = wid & 3;          // warp m index 0..3 (32 rows each)
    int wn   = wid >> 2;         // warp n index 0..1 (64 cols each)
    size_t m0 = (size_t)blockIdx.y * 128;
    size_t n0 = (size_t)blockIdx.x * 128;

    int arow = tid >> 1;         // 0..127
    int ak   = (tid & 1) * 8;    // 0 or 8
    int brow = tid >> 4;         // 0..15
    int bcol = (tid & 15) * 8;   // 0..120

    const float* Ap = A + (m0 + arow) * (size_t)lda + ak;
    const float* Bp = B + (size_t)brow * ldb + n0 + bcol;

    float4 a0n = *(const float4*)Ap;
    float4 a1n = *(const float4*)(Ap + 4);
    float4 b0n = *(const float4*)Bp;
    float4 b1n = *(const float4*)(Bp + 4);

    // prologue: fill stage 0
    *(uint4*)&As[0][arow * ALD + ak] =
        make_uint4(__float_as_uint(a0n.x), __float_as_uint(a1n.x),
                   __float_as_uint(a0n.y), __float_as_uint(a1n.y));
    *(uint4*)&As[0][arow * ALD + ak + 4] =
        make_uint4(__float_as_uint(a0n.z), __float_as_uint(a1n.z),
                   __float_as_uint(a0n.w), __float_as_uint(a1n.w));
    *(uint4*)&Bs[0][brow * GLD + bcol] =
        make_uint4(__float_as_uint(b0n.x), __float_as_uint(b0n.y),
                   __float_as_uint(b0n.z), __float_as_uint(b0n.w));
    *(uint4*)&Bs[0][brow * GLD + bcol + 4] =
        make_uint4(__float_as_uint(b1n.x), __float_as_uint(b1n.y),
                   __float_as_uint(b1n.z), __float_as_uint(b1n.w));
    __syncthreads();

    float acc[2][8][4];
    #pragma unroll
    for (int mt = 0; mt < 2; mt++)
        #pragma unroll
        for (int nt = 0; nt < 8; nt++)
            #pragma unroll
            for (int r = 0; r < 4; r++) acc[mt][nt][r] = 0.f;

    int ar = lane >> 2;          // 0..7
    int ac = lane & 3;           // 0..3
    int buf = 0;

    for (int k0 = 0; k0 < K; k0 += 16) {
        bool more = (k0 + 16 < K);
        if (more) {
            a0n = *(const float4*)(Ap + k0 + 16);
            a1n = *(const float4*)(Ap + k0 + 20);
            b0n = *(const float4*)(Bp + (size_t)(k0 + 16) * ldb);
            b1n = *(const float4*)(Bp + (size_t)(k0 + 16) * ldb + 4);
        }

        const uint32_t* Ab = As[buf];
        const uint32_t* Bb = Bs[buf];
        #pragma unroll
        for (int kk = 0; kk < 16; kk += 8) {
            uint32_t afr[2][4];
            #pragma unroll
            for (int mt = 0; mt < 2; mt++) {
                int mb = wm * 32 + mt * 16;
                uint2 u = *(const uint2*)&Ab[(mb + ar) * ALD + kk + 2 * ac];
                uint2 v = *(const uint2*)&Ab[(mb + 8 + ar) * ALD + kk + 2 * ac];
                afr[mt][0] = u.x; afr[mt][1] = v.x;
                afr[mt][2] = u.y; afr[mt][3] = v.y;
            }
            uint32_t bfr[8][2];
            #pragma unroll
            for (int nt = 0; nt < 8; nt++) {
                int nb = wn * 64 + nt * 8;
                bfr[nt][0] = Bb[(kk + ac) * GLD + nb + ar];
                bfr[nt][1] = Bb[(kk + 4 + ac) * GLD + nb + ar];
            }
            #pragma unroll
            for (int mt = 0; mt < 2; mt++)
                #pragma unroll
                for (int nt = 0; nt < 8; nt++)
                    mma_tf32(acc[mt][nt], afr[mt], bfr[nt]);
        }

        if (more) {
            int nb_ = buf ^ 1;
            *(uint4*)&As[nb_][arow * ALD + ak] =
                make_uint4(__float_as_uint(a0n.x), __float_as_uint(a1n.x),
                           __float_as_uint(a0n.y), __float_as_uint(a1n.y));
            *(uint4*)&As[nb_][arow * ALD + ak + 4] =
                make_uint4(__float_as_uint(a0n.z), __float_as_uint(a1n.z),
                           __float_as_uint(a0n.w), __float_as_uint(a1n.w));
            *(uint4*)&Bs[nb_][brow * GLD + bcol] =
                make_uint4(__float_as_uint(b0n.x), __float_as_uint(b0n.y),
                           __float_as_uint(b0n.z), __float_as_uint(b0n.w));
            *(uint4*)&Bs[nb_][brow * GLD + bcol + 4] =
                make_uint4(__float_as_uint(b1n.x), __float_as_uint(b1n.y),
                           __float_as_uint(b1n.z), __float_as_uint(b1n.w));
            __syncthreads();
            buf = nb_;
        }
    }

    #pragma unroll
    for (int mt = 0; mt < 2; mt++) {
        size_t row = m0 + wm * 32 + mt * 16 + ar;
        #pragma unroll
        for (int nt = 0; nt < 8; nt++) {
            size_t col = n0 + wn * 64 + nt * 8 + ac * 2;
            *(float2*)&C[row * (size_t)ldc + col] =
                make_float2(acc[mt][nt][0], acc[mt][nt][1]);
            *(float2*)&C[(row + 8) * (size_t)ldc + col] =
                make_float2(acc[mt][nt][2], acc[mt][nt][3]);
        }
    }
}

// ---------------- RoPE + RMSNorm (q,k) and gated ve add (v), in place -----
__global__ __launch_bounds__(256)
void post_kernel(const float* __restrict__ x, const float* __restrict__ ve,
                 const float* __restrict__ cosb, const float* __restrict__ sinb,
                 const float* __restrict__ Wg, float* __restrict__ qkv)
{
    int wid  = (blockIdx.x * blockDim.x + threadIdx.x) >> 5;
    int lane = threadIdx.x & 31;
    int row = wid / 18;
    int t   = wid - row * 18;
    if (row >= MROWS) return;
    int s = row & (SS - 1);

    if (t < 17) {
        float* vec = qkv + (size_t)row * NQKV + (t < 16 ? t * 64 : 1024);
        float c  = cosb[s * HALF + lane];
        float sn = sinb[s * HALF + lane];
        float x1 = vec[lane];
        float x2 = vec[lane + 32];
        float y1 = x1 * c + x2 * sn;
        float y2 = x2 * c - x1 * sn;
        float ssum = y1 * y1 + y2 * y2;
        #pragma unroll
        for (int off = 16; off; off >>= 1)
            ssum += __shfl_xor_sync(0xffffffffu, ssum, off);
        float sc = rsqrtf(ssum * (1.0f / 64.0f) + EPSF);
        vec[lane]      = y1 * sc;
        vec[lane + 32] = y2 * sc;
    } else {
        float g = x[(size_t)row * EE + lane] * Wg[lane];
        #pragma unroll
        for (int off = 16; off; off >>= 1)
            g += __shfl_xor_sync(0xffffffffu, g, off);
        float gate = 2.0f / (1.0f + __expf(-g));
        float* vvec = qkv + (size_t)row * NQKV + 1088;
        const float* veb = ve + (size_t)row * DD;
        vvec[lane]      += gate * veb[lane];
        vvec[lane + 32] += gate * veb[lane + 32];
    }
}

// ---------------- windowed-causal flash attention, tf32 tensor cores v6 --
// v4 structure + FIXED-MAX softmax: q,k are rmsnormed (norm 8 each), so
// scores = q.k/8 are bounded in [-8, 8]. Softmax is shift-invariant ->
// use constant max 8.0: p = exp(s - 8) in [e^-16, 1]. No online max, no
// corr rescale, no m tracking, no dead-row special cases. O accumulates
// unrescaled; final divide by l gives the exact softmax.
#define TS 72
#define ATT_SMEM ((4 * 64 * TS) * 4)
#define SMAX 8.0f

__global__ __launch_bounds__(128)
void attn_kernel(const float* __restrict__ qkv, float* __restrict__ out,
                 const int* __restrict__ wptr)
{
    extern __shared__ uint32_t smu[];
    uint32_t* Qs = smu;                  // [64 q][TS]   k-permuted d cols
    uint32_t* Ks = Qs + 64 * TS;         // [64 key][TS] k-permuted d cols
    uint32_t* Vs = Ks + 64 * TS;         // [64 key][TS] natural
    uint32_t* Ps = Vs + 64 * TS;         // [64 q][TS]   k-permuted key cols

    const int window = *wptr;
    int tid  = threadIdx.x;
    int lane = tid & 31;
    int wid  = tid >> 5;          // 0..3
    int mb   = wid * 16;          // warp's q-block base (16 rows)
    int ar   = lane >> 2;         // 0..7
    int ac   = lane & 3;          // 0..3
    int r0   = mb + ar;           // this thread's q rows within the tile
    int r1   = r0 + 8;

    int qt = (SS / 64 - 1) - blockIdx.x;   // heavy tiles first
    int h  = blockIdx.y;
    int b  = blockIdx.z;
    int q0 = qt * 64;
    const float* base = qkv + (size_t)b * SS * NQKV;

    // Ps store positions for this thread's (col 2ac, col 2ac+1) pair
    int pp0 = (ac < 2) ? 4 * ac : 4 * ac - 7;

    // load Q tile [q][d] k-permuted (scaled, tf32)
    #pragma unroll
    for (int it = 0; it < 8; it++) {
        int idx = tid + it * 128;          // 0..1023 uint4 stores
        int row = idx >> 4;
        int sub = idx & 15;
        int g = sub >> 1, hh = sub & 1;
        const float* src = &base[(size_t)(q0 + row) * NQKV + h * 64 + g * 8 + 2 * hh];
        float2 a = *(const float2*)src;
        float2 c = *(const float2*)(src + 4);
        *(uint4*)&Qs[row * TS + g * 8 + 4 * hh] =
            make_uint4(f2tf(a.x * 0.125f), f2tf(c.x * 0.125f),
                       f2tf(a.y * 0.125f), f2tf(c.y * 0.125f));
    }

    float of[8][4];
    #pragma unroll
    for (int nb = 0; nb < 8; nb++)
        #pragma unroll
        for (int c = 0; c < 4; c++) of[nb][c] = 0.f;
    float l0r = 0.f, l1r = 0.f;

    int lo = q0 - window + 1; if (lo < 0) lo = 0;
    int t_lo = lo >> 6;

    for (int t = t_lo; t <= qt; t++) {
        int k0 = t * 64;
        __syncthreads();   // protect Ks/Vs from previous-iteration readers
        // K tile: k-permuted (same scheme as Q)
        #pragma unroll
        for (int it = 0; it < 8; it++) {
            int idx = tid + it * 128;
            int row = idx >> 4;
            int sub = idx & 15;
            int g = sub >> 1, hh = sub & 1;
            const float* src = &base[(size_t)(k0 + row) * NQKV + 1024 + g * 8 + 2 * hh];
            float2 a = *(const float2*)src;
            float2 c = *(const float2*)(src + 4);
            *(uint4*)&Ks[row * TS + g * 8 + 4 * hh] =
                make_uint4(f2tf(a.x), f2tf(c.x), f2tf(a.y), f2tf(c.y));
        }
        // V tile: natural layout, float4 path
        #pragma unroll
        for (int it = 0; it < 8; it++) {
            int idx = tid + it * 128;
            int row = idx >> 4;
            int d4 = (idx & 15) << 2;
            float4 v = *(const float4*)&base[(size_t)(k0 + row) * NQKV + 1088 + d4];
            *(uint4*)&Vs[row * TS + d4] =
                make_uint4(f2tf(v.x), f2tf(v.y), f2tf(v.z), f2tf(v.w));
        }
        __syncthreads();

        // ---- S = Q K^T on tensor cores (warp-local 16q x 64k) ----
        float sf[8][4];
        #pragma unroll
        for (int nb = 0; nb < 8; nb++)
            #pragma unroll
            for (int c = 0; c < 4; c++) sf[nb][c] = 0.f;
        #pragma unroll
        for (int kk = 0; kk < 64; kk += 8) {
            uint2 qa = *(const uint2*)&Qs[r0 * TS + kk + 2 * ac];
            uint2 qb = *(const uint2*)&Qs[r1 * TS + kk + 2 * ac];
            uint32_t afr[4] = {qa.x, qb.x, qa.y, qb.y};
            #pragma unroll
            for (int nb = 0; nb < 8; nb++) {
                int key = nb * 8 + ar;
                uint2 kv = *(const uint2*)&Ks[key * TS + kk + 2 * ac];
                uint32_t bfr[2] = {kv.x, kv.y};
                mma_tf32(sf[nb], afr, bfr);
            }
        }

        // ---- mask (boundary tiles only) ----
        bool need_mask = (k0 + 63 > q0) || (q0 + 63 - k0 >= window);
        if (need_mask) {
            int qg0 = q0 + r0, qg1 = q0 + r1;
            #pragma unroll
            for (int nb = 0; nb < 8; nb++) {
                int kg = k0 + nb * 8 + ac * 2;
                #pragma unroll
                for (int cc = 0; cc < 2; cc++) {
                    int kk = kg + cc;
                    int d0 = qg0 - kk, d1 = qg1 - kk;
                    if (d0 < 0 || d0 >= window) sf[nb][cc]     = -INFINITY;
                    if (d1 < 0 || d1 >= window) sf[nb][2 + cc] = -INFINITY;
                }
            }
        }

        // ---- fixed-max softmax: p = exp(s - 8), no rescaling ever ----
        float hs0 = 0.f, hs1 = 0.f;
        #pragma unroll
        for (int nb = 0; nb < 8; nb++) {
            int gbase = nb * 8;             // key group base
            float p0 = __expf(sf[nb][0] - SMAX);   // masked -> exp(-inf)=0
            float p1 = __expf(sf[nb][1] - SMAX);
            float p2 = __expf(sf[nb][2] - SMAX);
            float p3 = __expf(sf[nb][3] - SMAX);
            hs0 += p0 + p1;
            hs1 += p2 + p3;
            Ps[r0 * TS + gbase + pp0]     = f2tf(p0);
            Ps[r0 * TS + gbase + pp0 + 2] = f2tf(p1);
            Ps[r1 * TS + gbase + pp0]     = f2tf(p2);
            Ps[r1 * TS + gbase + pp0 + 2] = f2tf(p3);
        }
        hs0 += __shfl_xor_sync(0xffffffffu, hs0, 1);
        hs0 += __shfl_xor_sync(0xffffffffu, hs0, 2);
        hs1 += __shfl_xor_sync(0xffffffffu, hs1, 1);
        hs1 += __shfl_xor_sync(0xffffffffu, hs1, 2);
        l0r += hs0;
        l1r += hs1;
        __syncwarp();   // Ps rows are warp-private

        // ---- O += P @ V on tensor cores (warp-local 16q x 64d) ----
        #pragma unroll
        for (int kk = 0; kk < 64; kk += 8) {
            uint2 pa = *(const uint2*)&Ps[r0 * TS + kk + 2 * ac];
            uint2 pb = *(const uint2*)&Ps[r1 * TS + kk + 2 * ac];
            uint32_t afr[4] = {pa.x, pb.x, pa.y, pb.y};
            #pragma unroll
            for (int nb = 0; nb < 8; nb++) {
                uint32_t bfr[2];
                bfr[0] = Vs[(kk + ac) * TS + nb * 8 + ar];
                bfr[1] = Vs[(kk + 4 + ac) * TS + nb * 8 + ar];
                mma_tf32(of[nb], afr, bfr);
            }
        }
    }

    // ---- finalize + write tf32 BITS (g_attn feeds gemm2's A operand) ----
    float inv0 = 1.0f / l0r;
    float inv1 = 1.0f / l1r;
    size_t row0 = (size_t)b * SS + q0 + r0;
    size_t row1 = (size_t)b * SS + q0 + r1;
    #pragma unroll
    for (int nb = 0; nb < 8; nb++) {
        size_t col = h * 64 + nb * 8 + ac * 2;
        *(float2*)&out[row0 * EE + col] =
            make_float2(__uint_as_float(f2tf(of[nb][0] * inv0)),
                        __uint_as_float(f2tf(of[nb][1] * inv0)));
        *(float2*)&out[row1 * EE + col] =
            make_float2(__uint_as_float(f2tf(of[nb][2] * inv1)),
                        __uint_as_float(f2tf(of[nb][3] * inv1)));
    }
}

// ---------------- launch ----------------
extern "C" void kernel_launch(void* const* d_in, const int* in_sizes, int n_in,
                              void* d_out, int out_size)
{
    const float* x    = (const float*)d_in[0];
    const float* ve   = (const float*)d_in[1];
    const float* cosb = (const float*)d_in[2];
    const float* sinb = (const float*)d_in[3];
    const float* Wq   = (const float*)d_in[4];
    const float* Wk   = (const float*)d_in[5];
    const float* Wv   = (const float*)d_in[6];
    const float* Wo   = (const float*)d_in[7];
    const float* Wg   = (const float*)d_in[8];
    const int*   win  = (const int*)d_in[9];
    float* out = (float*)d_out;

    float *wqkv, *wo_tf, *xtf, *qkv, *attn;
    cudaGetSymbolAddress((void**)&wqkv,  g_Wqkv);
    cudaGetSymbolAddress((void**)&wo_tf, g_Wo);
    cudaGetSymbolAddress((void**)&xtf,   g_xtf);
    cudaGetSymbolAddress((void**)&qkv,   g_qkv);
    cudaGetSymbolAddress((void**)&attn,  g_attn);

    cudaFuncSetAttribute(attn_kernel,
                         cudaFuncAttributeMaxDynamicSharedMemorySize,
                         (int)ATT_SMEM);

    // 1. pre-convert all GEMM inputs to tf32 bits
    pack_kernel<<<(1024 * NQKV + 255) / 256, 256>>>(Wq, Wk, Wv, wqkv);
    conv_tf_kernel<<<(MROWS * EE + 255) / 256, 256>>>(x, xtf, MROWS * EE);
    conv_tf_kernel<<<(EE * EE + 255) / 256, 256>>>(Wo, wo_tf, EE * EE);

    // 2. fused QKV projection: [4096,1024] @ [1024,1152]  (tf32, 2-stage)
    gemm_tf32<<<dim3(NQKV / 128, MROWS / 128), 256>>>(xtf, wqkv, qkv,
                                                      1024, 1024, NQKV, NQKV);

    // 3. rope + rmsnorm (q,k), gated ve add (v)
    post_kernel<<<(MROWS * 18) / 8, 256>>>(x, ve, cosb, sinb, Wg, qkv);

    // 4. attention (tf32 tensor core, fixed-max softmax)
    attn_kernel<<<dim3(SS / 64, HH, BB), 128, ATT_SMEM>>>(qkv, attn, win);

    // 5. output projection: [4096,1024] @ [1024,1024]  (tf32, 2-stage)
    gemm_tf32<<<dim3(EE / 128, MROWS / 128), 256>>>(attn, wo_tf, out,
                                                    1024, 1024, EE, EE);
}